// round 6
// baseline (speedup 1.0000x reference)
#include <cuda_runtime.h>
#include <cuda_bf16.h>

#define N_IN       16
#define FANIN      16
#define N_NODES    512
#define N_OUT      64
#define BATCH      32768
#define OUT_START  (N_NODES - N_OUT)   // node 448

#define THREADS    256
#define GRID       (BATCH / THREADS)   // 128 CTAs, one wave, 2 warps/SMSP

// All per-node parameters live in the constant bank: every thread in every
// warp reads the SAME address each node, so these become uniform-datapath
// loads (LDCU -> UR operands), bypassing the shared-memory crossbar that
// bounded rounds 1-5 (l1tex ~57%).
__constant__ float4 cW[N_NODES * 4];   // [512][16] weights, 32 KB
__constant__ float  cB[N_NODES];       // bias, 2 KB
__constant__ float  cR[N_NODES];       // response, 2 KB

__device__ __forceinline__ float tanh_approx(float x) {
    float y; asm("tanh.approx.f32 %0, %1;" : "=f"(y) : "f"(x)); return y;
}

__global__ void __launch_bounds__(THREADS, 1)
neat_forward_const(const float* __restrict__ x,
                   float*       __restrict__ out)    // [BATCH][64]
{
    const int b = blockIdx.x * THREADS + threadIdx.x;   // one batch element/thread

    // Circular register window: v[g & 15] = value at global index g
    // (inputs raw; compute nodes store tanh(.)*resp, i.e. the true node value).
    // Node i (j = i & 15) reads v[(j+t)&15], t=0..15 (t=15 newest), writes v[j].
    float v[16];
    {
        const float4* xv = (const float4*)(x + (size_t)b * N_IN);
        #pragma unroll
        for (int q = 0; q < 4; q++) {
            float4 t = xv[q];
            v[4*q+0] = t.x; v[4*q+1] = t.y; v[4*q+2] = t.z; v[4*q+3] = t.w;
        }
    }

    float* outp = out + (size_t)b * N_OUT;

    #pragma unroll 1
    for (int g = 0; g < N_NODES / 16; g++) {
        #pragma unroll
        for (int j = 0; j < 16; j++) {
            const int node = g * 16 + j;
            const float4 q0 = cW[node * 4 + 0];
            const float4 q1 = cW[node * 4 + 1];
            const float4 q2 = cW[node * 4 + 2];
            const float4 q3 = cW[node * 4 + 3];
            const float  bb = cB[node];
            const float  rr = cR[node];

            // Taps 0..14 depend on node-2 and older -> off the serial path,
            // they overlap the previous node's tanh. Tap 15 (newest) enters last.
            float a0 = fmaf(v[(j + 0)  & 15], q0.x, bb);
            float a1 =      v[(j + 1)  & 15] * q0.y;
            float a2 =      v[(j + 2)  & 15] * q0.z;
            float a3 =      v[(j + 3)  & 15] * q0.w;
            a0 = fmaf(v[(j + 4)  & 15], q1.x, a0);
            a1 = fmaf(v[(j + 5)  & 15], q1.y, a1);
            a2 = fmaf(v[(j + 6)  & 15], q1.z, a2);
            a3 = fmaf(v[(j + 7)  & 15], q1.w, a3);
            a0 = fmaf(v[(j + 8)  & 15], q2.x, a0);
            a1 = fmaf(v[(j + 9)  & 15], q2.y, a1);
            a2 = fmaf(v[(j + 10) & 15], q2.z, a2);
            a3 = fmaf(v[(j + 11) & 15], q2.w, a3);
            a0 = fmaf(v[(j + 12) & 15], q3.x, a0);
            a1 = fmaf(v[(j + 13) & 15], q3.y, a1);
            a2 = fmaf(v[(j + 14) & 15], q3.z, a2);
            const float partial = (a0 + a1) + (a2 + a3);

            // Serial path per node: fma -> tanh -> mul(resp).
            const float agg = fmaf(v[(j + 15) & 15], q3.w, partial);
            const float y   = tanh_approx(agg) * rr;
            v[j] = y;

            if (g >= OUT_START / 16) {
                outp[node - OUT_START] = y;     // window value IS the output
            }
        }
    }
}

extern "C" void kernel_launch(void* const* d_in, const int* in_sizes, int n_in,
                              void* d_out, int out_size) {
    const float* x    = (const float*)d_in[0];   // [BATCH, 16]
    const float* w    = (const float*)d_in[1];   // [512, 16]
    const float* bias = (const float*)d_in[2];   // [512]
    const float* resp = (const float*)d_in[3];   // [512]
    // d_in[4] (src_idx) is the fixed sliding-window topology; baked into indexing.
    float* out = (float*)d_out;                  // [BATCH, 64]

    // Stage parameters into the constant bank (async D2D, graph-capturable).
    cudaMemcpyToSymbolAsync(cW, w,    N_NODES * FANIN * sizeof(float), 0,
                            cudaMemcpyDeviceToDevice, 0);
    cudaMemcpyToSymbolAsync(cB, bias, N_NODES * sizeof(float), 0,
                            cudaMemcpyDeviceToDevice, 0);
    cudaMemcpyToSymbolAsync(cR, resp, N_NODES * sizeof(float), 0,
                            cudaMemcpyDeviceToDevice, 0);

    neat_forward_const<<<GRID, THREADS>>>(x, out);
}

// round 8
// speedup vs baseline: 2.1243x; 2.1243x over previous
#include <cuda_runtime.h>
#include <cuda_bf16.h>
#include <cstdint>

#define N_IN       16
#define FANIN      16
#define N_NODES    512
#define N_OUT      64
#define BATCH      32768
#define OUT_START  (N_NODES - N_OUT)   // node 448

#define THREADS    256
#define GRID       (BATCH / THREADS)   // 128 CTAs, one wave, 2 warps/SMSP

#define PAD_NODES  (N_NODES + 2)       // 2 zero pad rows for distance-2 prefetch tail

using u32 = unsigned int;

__device__ __forceinline__ float tanh_approx(float x) {
    float y; asm("tanh.approx.f32 %0, %1;" : "=f"(y) : "f"(x)); return y;
}
__device__ __forceinline__ u32 smem_u32(const void* p) {
    u32 a;
    asm("{ .reg .u64 t; cvta.to.shared.u64 t, %1; cvt.u32.u64 %0, t; }"
        : "=r"(a) : "l"(p));
    return a;
}
// Volatile shared loads: ptxas cannot sink/merge these — this is what makes
// the software pipeline REAL (R5's C++-level rotation was coalesced away).
__device__ __forceinline__ void lds_v4(float4& d, u32 addr) {
    asm volatile("ld.shared.v4.f32 {%0,%1,%2,%3}, [%4];"
                 : "=f"(d.x), "=f"(d.y), "=f"(d.z), "=f"(d.w) : "r"(addr));
}
__device__ __forceinline__ void lds_f32(float& d, u32 addr) {
    asm volatile("ld.shared.f32 %0, [%1];" : "=f"(d) : "r"(addr));
}

// Shared memory (float units):
//   [0, PAD_NODES*16)  : resp-folded weights w'[node][tap] (+2 zero rows)
//   [.., +PAD_NODES)   : bias per node (+2 pad)
//   [.., +N_OUT)       : resp for the 64 output nodes
#define SMEM_W   0
#define SMEM_B   (PAD_NODES * FANIN)
#define SMEM_R   (SMEM_B + PAD_NODES)
#define SMEM_F32 (SMEM_R + N_OUT)

struct WBuf { float4 q0, q1, q2, q3; float b; };

__global__ void __launch_bounds__(THREADS, 1)
neat_forward_pipe2(const float* __restrict__ x,
                   const float* __restrict__ w,      // [512][16]
                   const float* __restrict__ bias,   // [512]
                   const float* __restrict__ resp,   // [512]
                   float*       __restrict__ out)    // [BATCH][64]
{
    extern __shared__ __align__(16) float sh[];
    const int tid = threadIdx.x;

    // Fold each source's response into the consumer weight:
    //   w'[i][t] = w[i][t] * resp[i + t - 16]   (identity for input sources).
    // Window carries RAW tanh values; resp applied only at output stores.
    for (int i = tid; i < N_NODES * FANIN; i += THREADS) {
        const int node = i >> 4, t = i & 15;
        const int g = node + t;
        const float s = (g >= N_IN) ? resp[g - N_IN] : 1.0f;
        sh[SMEM_W + i] = w[i] * s;
    }
    // zero pad rows (nodes 512, 513) so tail prefetches are in-bounds
    for (int i = tid; i < 2 * FANIN; i += THREADS) sh[SMEM_W + N_NODES * FANIN + i] = 0.0f;
    for (int i = tid; i < N_NODES; i += THREADS) sh[SMEM_B + i] = bias[i];
    if (tid < 2) sh[SMEM_B + N_NODES + tid] = 0.0f;
    for (int i = tid; i < N_OUT; i += THREADS) sh[SMEM_R + i] = resp[OUT_START + i];
    __syncthreads();

    const int b = blockIdx.x * THREADS + tid;       // one batch element per thread

    // Circular register window: v[g & 15] = value at global index g.
    float v[16];
    {
        const float4* xv = (const float4*)(x + (size_t)b * N_IN);
        #pragma unroll
        for (int q = 0; q < 4; q++) {
            float4 t = xv[q];
            v[4*q+0] = t.x; v[4*q+1] = t.y; v[4*q+2] = t.z; v[4*q+3] = t.w;
        }
    }

    float* outp = out + (size_t)b * N_OUT;

    const u32 waddr = smem_u32(sh + SMEM_W);   // row stride 64 B
    const u32 baddr = smem_u32(sh + SMEM_B);

    // 4-buffer ring, distance-2 prefetch. Node n computes from wb[n & 3];
    // at the TOP of node n's block we prefetch node n+2 into wb[(n+2)&3],
    // a buffer last read at node n-2 — no WAR against the current block.
    WBuf wb[4];
    #pragma unroll
    for (int s = 0; s < 2; s++) {                   // prologue: nodes 0 and 1
        lds_v4(wb[s].q0, waddr + s * 64 + 0);
        lds_v4(wb[s].q1, waddr + s * 64 + 16);
        lds_v4(wb[s].q2, waddr + s * 64 + 32);
        lds_v4(wb[s].q3, waddr + s * 64 + 48);
        lds_f32(wb[s].b, baddr + s * 4);
    }

    #pragma unroll 1
    for (int g = 0; g < N_NODES / 16; g++) {
        #pragma unroll
        for (int j = 0; j < 16; j++) {              // node = g*16 + j ; stage = j & 3
            const int node = g * 16 + j;
            const int cs = j & 3;                   // compute stage (static)
            const int ps = (j + 2) & 3;             // prefetch stage (static)

            // --- prefetch node+2 (volatile: cannot be sunk) ---
            const u32 pw = waddr + (u32)(node + 2) * 64;
            lds_v4(wb[ps].q0, pw + 0);
            lds_v4(wb[ps].q1, pw + 16);
            lds_v4(wb[ps].q2, pw + 32);
            lds_v4(wb[ps].q3, pw + 48);
            lds_f32(wb[ps].b, baddr + (u32)(node + 2) * 4);

            // --- compute node from wb[cs] (loaded 2 nodes ago) ---
            const float4 q0 = wb[cs].q0, q1 = wb[cs].q1;
            const float4 q2 = wb[cs].q2, q3 = wb[cs].q3;
            const float  bb = wb[cs].b;

            // Taps 0..14 depend on node-2 and older -> off the serial path.
            float a0 = fmaf(v[(j + 0)  & 15], q0.x, bb);
            float a1 =      v[(j + 1)  & 15] * q0.y;
            float a2 =      v[(j + 2)  & 15] * q0.z;
            float a3 =      v[(j + 3)  & 15] * q0.w;
            a0 = fmaf(v[(j + 4)  & 15], q1.x, a0);
            a1 = fmaf(v[(j + 5)  & 15], q1.y, a1);
            a2 = fmaf(v[(j + 6)  & 15], q1.z, a2);
            a3 = fmaf(v[(j + 7)  & 15], q1.w, a3);
            a0 = fmaf(v[(j + 8)  & 15], q2.x, a0);
            a1 = fmaf(v[(j + 9)  & 15], q2.y, a1);
            a2 = fmaf(v[(j + 10) & 15], q2.z, a2);
            a3 = fmaf(v[(j + 11) & 15], q2.w, a3);
            a0 = fmaf(v[(j + 12) & 15], q3.x, a0);
            a1 = fmaf(v[(j + 13) & 15], q3.y, a1);
            a2 = fmaf(v[(j + 14) & 15], q3.z, a2);
            const float partial = (a0 + a1) + (a2 + a3);

            // Serial path: ONE fma + tanh.
            const float agg = fmaf(v[(j + 15) & 15], q3.w, partial);
            const float y = tanh_approx(agg);
            v[j] = y;

            if (g >= OUT_START / 16) {
                const int o = node - OUT_START;
                outp[o] = y * sh[SMEM_R + o];       // resp applied off-path
            }
        }
    }
}

extern "C" void kernel_launch(void* const* d_in, const int* in_sizes, int n_in,
                              void* d_out, int out_size) {
    const float* x    = (const float*)d_in[0];   // [BATCH, 16]
    const float* w    = (const float*)d_in[1];   // [512, 16]
    const float* bias = (const float*)d_in[2];   // [512]
    const float* resp = (const float*)d_in[3];   // [512]
    // d_in[4] (src_idx) is the fixed sliding-window topology; baked into indexing.
    float* out = (float*)d_out;                  // [BATCH, 64]

    const int smem_bytes = SMEM_F32 * (int)sizeof(float);   // ~35 KB
    neat_forward_pipe2<<<GRID, THREADS, smem_bytes>>>(x, w, bias, resp, out);
}